// round 5
// baseline (speedup 1.0000x reference)
#include <cuda_runtime.h>

#define S_DIM 100000
#define G_DIM 18000
#define H_DIM 256
#define E_DIM 600000
#define B_DIM 256

#define KT      8       // k-tiles in build_v (32 k's each)
#define CHUNKS  50      // gemv chunks along S (25000/50 = 500 float4 each)
#define ROWS    8       // gemv rows per phase
#define SCAT_BLOCKS 586 // ceil(150000/256)
#define C0_BLOCKS   9   // const0 tail blocks (2000 g's each)

// One contiguous scratch block: [0,G) = v, [G, G+S) = coef, [G+S] = const0.
// Zeroed by a single cudaMemsetAsync each launch.
__device__ float g_scratch[G_DIM + S_DIM + 1];
#define G_V     (g_scratch)
#define G_COEF  (g_scratch + G_DIM)
#define G_C0    (g_scratch + G_DIM + S_DIM)

// ---------------------------------------------------------------------------
// Kernel 1: v[g] += sum over 32-k tile of W1[k,g]*W2[k].  grid=(71, KT)
__global__ void k_build_v(const float* __restrict__ W1, const float* __restrict__ W2) {
    __shared__ float w2s[32];
    const int k0 = blockIdx.y * (H_DIM / KT);
    if (threadIdx.x < 32) w2s[threadIdx.x] = W2[k0 + threadIdx.x];
    __syncthreads();
    int g = blockIdx.x * blockDim.x + threadIdx.x;
    if (g >= G_DIM) return;
    float acc = 0.0f;
    #pragma unroll
    for (int k = 0; k < 32; k++)
        acc = fmaf(W1[(size_t)(k0 + k) * G_DIM + g], w2s[k], acc);
    atomicAdd(&G_V[g], acc);
}

// ---------------------------------------------------------------------------
// Kernel 2: edge scatter (4 edges/thread, vectorized) + const0 tail blocks.
__global__ void k_scatter(const int* __restrict__ snp, const int* __restrict__ gidx,
                          const float* __restrict__ ew,
                          const float* __restrict__ gene_bias,
                          const float* __restrict__ b1, const float* __restrict__ W2,
                          const float* __restrict__ b2) {
    if (blockIdx.x < SCAT_BLOCKS) {
        int i4 = blockIdx.x * blockDim.x + threadIdx.x;     // quad index
        if (i4 >= E_DIM / 4) return;
        int4   s4 = reinterpret_cast<const int4*>(snp)[i4];
        int4   g4 = reinterpret_cast<const int4*>(gidx)[i4];
        float4 w4 = reinterpret_cast<const float4*>(ew)[i4];
        float v0 = G_V[g4.x], v1 = G_V[g4.y], v2 = G_V[g4.z], v3 = G_V[g4.w];
        atomicAdd(&G_COEF[s4.x], w4.x * v0);
        atomicAdd(&G_COEF[s4.y], w4.y * v1);
        atomicAdd(&G_COEF[s4.z], w4.z * v2);
        atomicAdd(&G_COEF[s4.w], w4.w * v3);
        return;
    }
    // ---- const0 tail ----
    int local = blockIdx.x - SCAT_BLOCKS;                   // 0..8
    int start = local * (G_DIM / C0_BLOCKS);                // 2000 per block
    float acc = 0.0f;
    for (int g = start + threadIdx.x; g < start + G_DIM / C0_BLOCKS; g += blockDim.x)
        acc = fmaf(G_V[g], gene_bias[g], acc);
    if (local == 0) {
        acc = fmaf(W2[threadIdx.x], b1[threadIdx.x], acc);  // blockDim == H_DIM
        if (threadIdx.x == 0) acc += b2[0];
    }
    __shared__ float sm[32];
    int lane = threadIdx.x & 31, wid = threadIdx.x >> 5;
    #pragma unroll
    for (int o = 16; o > 0; o >>= 1) acc += __shfl_down_sync(0xffffffffu, acc, o);
    if (lane == 0) sm[wid] = acc;
    __syncthreads();
    if (wid == 0) {
        acc = (lane < (blockDim.x >> 5)) ? sm[lane] : 0.0f;
        #pragma unroll
        for (int o = 16; o > 0; o >>= 1) acc += __shfl_down_sync(0xffffffffu, acc, o);
        if (lane == 0) atomicAdd(G_C0, acc);
    }
}

// ---------------------------------------------------------------------------
// Kernel 3: GEMV, single wave. grid=800 < 148*6=888 resident capacity:
// every block resident from t0, no wave transition, no tail.
// Block bid: chunk = bid%50, rg = bid/50 (0..15); processes row groups
// rg and rg+16 (8 rows each) over its 500-float4 chunk.
__global__ void __launch_bounds__(256, 6)
k_gemv(const float* __restrict__ x, float* __restrict__ out) {
    const int chunk = blockIdx.x % CHUNKS;
    const int rg    = blockIdx.x / CHUNKS;         // 0..15
    const int per   = (S_DIM / 4) / CHUNKS;        // 500
    const int base  = chunk * per;
    const float4* __restrict__ cf = reinterpret_cast<const float4*>(G_COEF);

    __shared__ float sm[ROWS][8];
    const int lane = threadIdx.x & 31, wid = threadIdx.x >> 5;
    const float c0 = *G_C0;

    #pragma unroll
    for (int phase = 0; phase < 2; phase++) {
        const int r0 = (rg + phase * 16) * ROWS;   // rows r0..r0+7
        float acc[ROWS];
        #pragma unroll
        for (int j = 0; j < ROWS; j++) acc[j] = 0.0f;

        #pragma unroll
        for (int it = 0; it < 2; it++) {
            int off = it * 256 + threadIdx.x;
            if (off < per) {
                int i = base + off;
                float4 cv = __ldg(&cf[i]);
                #pragma unroll
                for (int j = 0; j < ROWS; j++) {
                    float4 xv = __ldcs(reinterpret_cast<const float4*>(
                                    x + (size_t)(r0 + j) * S_DIM) + i);
                    acc[j] += xv.x * cv.x + xv.y * cv.y + xv.z * cv.z + xv.w * cv.w;
                }
            }
        }

        #pragma unroll
        for (int j = 0; j < ROWS; j++) {
            float v = acc[j];
            #pragma unroll
            for (int o = 16; o > 0; o >>= 1) v += __shfl_down_sync(0xffffffffu, v, o);
            if (lane == 0) sm[j][wid] = v;
        }
        __syncthreads();
        if (threadIdx.x < ROWS * 8) {
            int j = threadIdx.x >> 3, w = threadIdx.x & 7;
            float v = sm[j][w];
            #pragma unroll
            for (int o = 4; o > 0; o >>= 1) v += __shfl_down_sync(0xffffffffu, v, o);
            if (w == 0) {
                if (chunk == 0) v += c0;   // each row hit by exactly one chunk-0 block
                atomicAdd(&out[r0 + j], v);
            }
        }
        __syncthreads();   // protect sm reuse across phases
    }
}

// ---------------------------------------------------------------------------
extern "C" void kernel_launch(void* const* d_in, const int* in_sizes, int n_in,
                              void* d_out, int out_size) {
    const float* x    = (const float*)d_in[0];
    const int*   snp  = (const int*)  d_in[1];
    const int*   gidx = (const int*)  d_in[2];
    const float* ew   = (const float*)d_in[3];
    const float* gb   = (const float*)d_in[4];
    const float* W1   = (const float*)d_in[5];
    const float* b1   = (const float*)d_in[6];
    const float* W2   = (const float*)d_in[7];
    const float* b2   = (const float*)d_in[8];
    float* out = (float*)d_out;

    void* scratch_ptr = nullptr;
    cudaGetSymbolAddress(&scratch_ptr, g_scratch);
    cudaMemsetAsync(scratch_ptr, 0, (G_DIM + S_DIM + 1) * sizeof(float));
    cudaMemsetAsync(out, 0, B_DIM * sizeof(float));

    k_build_v<<<dim3((G_DIM + 255) / 256, KT), 256>>>(W1, W2);
    k_scatter<<<SCAT_BLOCKS + C0_BLOCKS, 256>>>(snp, gidx, ew, gb, b1, W2, b2);
    k_gemv<<<800, 256>>>(x, out);
}

// round 6
// speedup vs baseline: 1.1682x; 1.1682x over previous
#include <cuda_runtime.h>

#define S_DIM 100000
#define G_DIM 18000
#define H_DIM 256
#define E_DIM 600000
#define B_DIM 256

#define KT      16     // k-tiles in build_v
#define KS      16     // k's per tile (KT*KS = H_DIM)
#define G4_DIM  4500   // G_DIM/4 float4 columns
#define CHUNKS  50     // gemv chunks along S (25000/50 = 500 float4 each)
#define ROWS    8      // gemv rows per block
#define SCAT_BLOCKS 586   // ceil(150000/256)
#define C0_BLOCKS   9     // const0 tail blocks (2000 g's each)

__device__ float g_v[G_DIM];
__device__ float g_coef[S_DIM];
__device__ float g_const0;

// ---------------------------------------------------------------------------
// Kernel 1 (tiny): zero g_v, out, const0. (coef zeroed inside k_build_v.)
__global__ void k_prep(float* __restrict__ out) {
    int i = blockIdx.x * blockDim.x + threadIdx.x;   // 72*256 = 18432
    if (i < G_DIM) g_v[i] = 0.0f;
    if (i < B_DIM) out[i] = 0.0f;
    if (i == 0)    g_const0 = 0.0f;
}

// ---------------------------------------------------------------------------
// Kernel 2: grid=(36, KT+1), block=128.
//   y <  KT : v[4g..4g+3] += sum over 16-k tile of W1[k, 4g..4g+3]*W2[k]
//             (float4 loads: 16 independent 16B loads in flight per thread)
//   y == KT : zero coef (runs before k_scatter's atomics by stream order)
__global__ void k_build_v(const float* __restrict__ W1, const float* __restrict__ W2) {
    if (blockIdx.y == KT) {
        float4 z = make_float4(0.f, 0.f, 0.f, 0.f);
        float4* c4 = reinterpret_cast<float4*>(g_coef);
        for (int i = blockIdx.x * blockDim.x + threadIdx.x; i < S_DIM / 4; i += 36 * 128)
            c4[i] = z;
        return;
    }
    __shared__ float w2s[KS];
    const int k0 = blockIdx.y * KS;
    if (threadIdx.x < KS) w2s[threadIdx.x] = W2[k0 + threadIdx.x];
    __syncthreads();
    int g4 = blockIdx.x * blockDim.x + threadIdx.x;   // 0..4607
    if (g4 >= G4_DIM) return;
    const float4* __restrict__ W14 = reinterpret_cast<const float4*>(W1);
    float4 acc = make_float4(0.f, 0.f, 0.f, 0.f);
    #pragma unroll
    for (int k = 0; k < KS; k++) {
        float4 w = __ldg(&W14[(size_t)(k0 + k) * G4_DIM + g4]);
        float s = w2s[k];
        acc.x = fmaf(w.x, s, acc.x);
        acc.y = fmaf(w.y, s, acc.y);
        acc.z = fmaf(w.z, s, acc.z);
        acc.w = fmaf(w.w, s, acc.w);
    }
    float* vo = &g_v[g4 * 4];
    atomicAdd(vo + 0, acc.x);
    atomicAdd(vo + 1, acc.y);
    atomicAdd(vo + 2, acc.z);
    atomicAdd(vo + 3, acc.w);
}

// ---------------------------------------------------------------------------
// Kernel 3: edge scatter (4 edges/thread, vectorized) + const0 tail blocks.
__global__ void k_scatter(const int* __restrict__ snp, const int* __restrict__ gidx,
                          const float* __restrict__ ew,
                          const float* __restrict__ gene_bias,
                          const float* __restrict__ b1, const float* __restrict__ W2,
                          const float* __restrict__ b2) {
    if (blockIdx.x < SCAT_BLOCKS) {
        int i4 = blockIdx.x * blockDim.x + threadIdx.x;     // quad index
        if (i4 >= E_DIM / 4) return;
        int4   s4 = reinterpret_cast<const int4*>(snp)[i4];
        int4   g4 = reinterpret_cast<const int4*>(gidx)[i4];
        float4 w4 = reinterpret_cast<const float4*>(ew)[i4];
        float v0 = g_v[g4.x], v1 = g_v[g4.y], v2 = g_v[g4.z], v3 = g_v[g4.w];
        atomicAdd(&g_coef[s4.x], w4.x * v0);
        atomicAdd(&g_coef[s4.y], w4.y * v1);
        atomicAdd(&g_coef[s4.z], w4.z * v2);
        atomicAdd(&g_coef[s4.w], w4.w * v3);
        return;
    }
    // ---- const0 tail ----
    int local = blockIdx.x - SCAT_BLOCKS;                   // 0..8
    int start = local * (G_DIM / C0_BLOCKS);                // 2000 per block
    float acc = 0.0f;
    for (int g = start + threadIdx.x; g < start + G_DIM / C0_BLOCKS; g += blockDim.x)
        acc = fmaf(g_v[g], gene_bias[g], acc);
    if (local == 0) {
        acc = fmaf(W2[threadIdx.x], b1[threadIdx.x], acc);  // blockDim == H_DIM
        if (threadIdx.x == 0) acc += b2[0];
    }
    __shared__ float sm[32];
    int lane = threadIdx.x & 31, wid = threadIdx.x >> 5;
    #pragma unroll
    for (int o = 16; o > 0; o >>= 1) acc += __shfl_down_sync(0xffffffffu, acc, o);
    if (lane == 0) sm[wid] = acc;
    __syncthreads();
    if (wid == 0) {
        acc = (lane < (blockDim.x >> 5)) ? sm[lane] : 0.0f;
        #pragma unroll
        for (int o = 16; o > 0; o >>= 1) acc += __shfl_down_sync(0xffffffffu, acc, o);
        if (lane == 0) atomicAdd(&g_const0, acc);
    }
}

// ---------------------------------------------------------------------------
// Kernel 4: GEMV (R4-proven version). grid=(CHUNKS, B/ROWS)=(50,32)=1600.
__global__ void __launch_bounds__(256, 6)
k_gemv(const float* __restrict__ x, float* __restrict__ out) {
    const int per  = (S_DIM / 4) / CHUNKS;         // 500
    const int base = blockIdx.x * per;
    const int r0   = blockIdx.y * ROWS;
    const float4* __restrict__ cf = reinterpret_cast<const float4*>(g_coef);

    float acc[ROWS];
    #pragma unroll
    for (int j = 0; j < ROWS; j++) acc[j] = 0.0f;

    #pragma unroll
    for (int it = 0; it < 2; it++) {
        int off = it * 256 + threadIdx.x;
        if (off < per) {
            int i = base + off;
            float4 cv = __ldg(&cf[i]);
            #pragma unroll
            for (int j = 0; j < ROWS; j++) {
                float4 xv = __ldcs(reinterpret_cast<const float4*>(
                                x + (size_t)(r0 + j) * S_DIM) + i);
                acc[j] += xv.x * cv.x + xv.y * cv.y + xv.z * cv.z + xv.w * cv.w;
            }
        }
    }

    __shared__ float sm[ROWS][8];
    int lane = threadIdx.x & 31, wid = threadIdx.x >> 5;
    #pragma unroll
    for (int j = 0; j < ROWS; j++) {
        float v = acc[j];
        #pragma unroll
        for (int o = 16; o > 0; o >>= 1) v += __shfl_down_sync(0xffffffffu, v, o);
        if (lane == 0) sm[j][wid] = v;
    }
    __syncthreads();
    if (threadIdx.x < ROWS * 8) {
        int j = threadIdx.x >> 3, w = threadIdx.x & 7;
        float v = sm[j][w];
        #pragma unroll
        for (int o = 4; o > 0; o >>= 1) v += __shfl_down_sync(0xffffffffu, v, o);
        if (w == 0) {
            if (blockIdx.x == 0) v += g_const0;    // exactly one chunk adds const0
            atomicAdd(&out[r0 + j], v);
        }
    }
}

// ---------------------------------------------------------------------------
extern "C" void kernel_launch(void* const* d_in, const int* in_sizes, int n_in,
                              void* d_out, int out_size) {
    const float* x    = (const float*)d_in[0];
    const int*   snp  = (const int*)  d_in[1];
    const int*   gidx = (const int*)  d_in[2];
    const float* ew   = (const float*)d_in[3];
    const float* gb   = (const float*)d_in[4];
    const float* W1   = (const float*)d_in[5];
    const float* b1   = (const float*)d_in[6];
    const float* W2   = (const float*)d_in[7];
    const float* b2   = (const float*)d_in[8];
    float* out = (float*)d_out;

    k_prep<<<72, 256>>>(out);
    k_build_v<<<dim3(36, KT + 1), 128>>>(W1, W2);
    k_scatter<<<SCAT_BLOCKS + C0_BLOCKS, 256>>>(snp, gidx, ew, gb, b1, W2, b2);
    k_gemv<<<dim3(CHUNKS, B_DIM / ROWS), 256>>>(x, out);
}